// round 3
// baseline (speedup 1.0000x reference)
#include <cuda_runtime.h>

#define NB 64
#define NE 64
#define NC 64
#define NO 20

// ---------------- device scratch (no allocs allowed) ----------------
__device__ float g_h1[(size_t)NB*NE*14*14*NC];   // conv1 raw relu out (205 MB)
__device__ float g_h2[(size_t)NB*NE*7*7*NC];     // conv2 raw relu out
__device__ float g_h3[(size_t)NB*NE*4*4*NC];     // conv3 raw relu out
__device__ float g_feat[NB*NE*NC];               // max-pooled raw conv4 relu
__device__ float g_sum[4*NC];
__device__ float g_sumsq[4*NC];
__device__ float g_scale[4*NC];                  // rsqrt(var+eps)
__device__ float g_bias[4*NC];                   // -mean*scale

// ---------------- zero stats + feat ----------------
__global__ void zero_kernel() {
    int i = blockIdx.x * 256 + threadIdx.x;
    if (i < 4*NC) { g_sum[i] = 0.f; g_sumsq[i] = 0.f; }
    if (i < NB*NE*NC) g_feat[i] = 0.f;
}

// ---------------- conv1: Cin=1, 28x28 -> 14x14x64 ----------------
__global__ __launch_bounds__(256) void conv1_kernel(const float* __restrict__ x,
                                                    const float* __restrict__ k1) {
    __shared__ float s_in[30*30];
    __shared__ float s_sum[NC];
    __shared__ float s_sq[NC];
    int be = blockIdx.x;
    int t = threadIdx.x;
    for (int i = t; i < 900; i += 256) s_in[i] = 0.f;
    if (t < NC) { s_sum[t] = 0.f; s_sq[t] = 0.f; }
    __syncthreads();
    const float* xp = x + (size_t)be * 784;
    for (int i = t; i < 784; i += 256) {
        int r = i / 28, c = i - r*28;
        s_in[(r+1)*30 + c + 1] = xp[i];
    }
    int cg = t & 15, ig = t >> 4;          // cg: 16 co-groups of 4, ig: 16 item groups
    int b = be >> 6;
    float4 w[9];
    const float4* kp = (const float4*)(k1 + (size_t)b * 576);
    #pragma unroll
    for (int j = 0; j < 9; j++) w[j] = kp[j*16 + cg];
    __syncthreads();
    float ls0=0,ls1=0,ls2=0,ls3=0, lq0=0,lq1=0,lq2=0,lq3=0;
    float* outp = g_h1 + (size_t)be * 196 * 64;
    for (int p = ig; p < 196; p += 16) {
        int oy = p / 14, ox = p - oy*14;
        float a0=0,a1=0,a2=0,a3=0;
        #pragma unroll
        for (int ky = 0; ky < 3; ky++)
        #pragma unroll
        for (int kx = 0; kx < 3; kx++) {
            float v = s_in[(2*oy+ky)*30 + 2*ox + kx];
            float4 ww = w[ky*3+kx];
            a0 = fmaf(v, ww.x, a0); a1 = fmaf(v, ww.y, a1);
            a2 = fmaf(v, ww.z, a2); a3 = fmaf(v, ww.w, a3);
        }
        a0 = fmaxf(a0, 0.f); a1 = fmaxf(a1, 0.f);
        a2 = fmaxf(a2, 0.f); a3 = fmaxf(a3, 0.f);
        ls0+=a0; ls1+=a1; ls2+=a2; ls3+=a3;
        lq0+=a0*a0; lq1+=a1*a1; lq2+=a2*a2; lq3+=a3*a3;
        ((float4*)(outp + p*64))[cg] = make_float4(a0,a1,a2,a3);
    }
    int co4 = cg*4;
    atomicAdd(&s_sum[co4+0], ls0); atomicAdd(&s_sum[co4+1], ls1);
    atomicAdd(&s_sum[co4+2], ls2); atomicAdd(&s_sum[co4+3], ls3);
    atomicAdd(&s_sq[co4+0], lq0); atomicAdd(&s_sq[co4+1], lq1);
    atomicAdd(&s_sq[co4+2], lq2); atomicAdd(&s_sq[co4+3], lq3);
    __syncthreads();
    if (t < NC) {
        atomicAdd(&g_sum[t], s_sum[t]);
        atomicAdd(&g_sumsq[t], s_sq[t]);
    }
}

// ---------------- per-layer BN stats finalize ----------------
__global__ void finalize_kernel(int layer, float invN) {
    int c = threadIdx.x;
    float s = g_sum[layer*NC + c];
    float q = g_sumsq[layer*NC + c];
    float m = s * invN;
    float v = q * invN - m*m;
    float sc = rsqrtf(v + 1e-3f);
    g_scale[layer*NC + c] = sc;
    g_bias[layer*NC + c] = -m * sc;
}

// ---------------- generic conv layers 2-4 (implicit GEMM per task) ----------------
// LNUM=1: h1(14x14) -> h2(7x7), stats layer0 folded into load, produces stats layer1
// LNUM=2: h2(7x7)   -> h3(4x4)
// LNUM=3: h3(4x4)   -> g_feat (max over 2x2), LAST
template<int LNUM>
__global__ __launch_bounds__(256, 2) void conv_kernel(const float* __restrict__ kw) {
    constexpr int HIN    = (LNUM==1) ? 14 : (LNUM==2) ? 7 : 4;
    constexpr int HOUT   = (LNUM==1) ? 7  : (LNUM==2) ? 4 : 2;
    constexpr int SPREV  = LNUM - 1;
    constexpr int TILE_M = (LNUM==3) ? 64 : 256;
    constexpr int IT     = (LNUM==3) ? 2  : 8;
    constexpr bool LAST  = (LNUM==3);
    constexpr int POS    = HOUT*HOUT;
    constexpr int MTASK  = NE*POS;

    extern __shared__ float sm[];
    float* sA   = sm;                    // TILE_M rows x 68 floats (64 used + pad)
    float* sB   = sm + TILE_M*68;        // 64 ci x 64 co
    float* s_sc = sB + 64*64;
    float* s_bi = s_sc + 64;
    float* s_sum= s_bi + 64;
    float* s_sq = s_sum + 64;

    const float* h_prev = (LNUM==1) ? g_h1 : (LNUM==2) ? g_h2 : g_h3;
    float* h_out        = (LNUM==1) ? g_h2 : g_h3;

    int b  = blockIdx.y;
    int m0 = blockIdx.x * TILE_M;
    int t  = threadIdx.x;
    if (t < 64) {
        s_sc[t] = g_scale[SPREV*NC + t];
        s_bi[t] = g_bias[SPREV*NC + t];
        s_sum[t] = 0.f; s_sq[t] = 0.f;
    }

    // loader assignment: PER threads cooperate per item row
    constexpr int PER  = 256 / TILE_M;
    constexpr int JCNT = 16 / PER;       // float4 per thread per item row
    int lm = t % TILE_M;
    int lq = t / TILE_M;
    int gi  = m0 + lm;
    int gic = min(gi, MTASK-1);
    int le  = gic / POS;
    int lp  = gic - le*POS;
    int loy = lp / HOUT, lox = lp - loy*HOUT;
    const float* inb = h_prev + ((size_t)(b*NE + le)*HIN*HIN)*64;

    // compute assignment: 8 co-groups x 32 item-groups, items strided by 32
    int cg = t & 7, ig = t >> 3;
    float acc[IT][8];
    #pragma unroll
    for (int i = 0; i < IT; i++)
        #pragma unroll
        for (int j = 0; j < 8; j++) acc[i][j] = 0.f;

    __syncthreads();

    const float4* wtask = (const float4*)(kw + (size_t)b*9*64*64);

    for (int kk = 0; kk < 9; kk++) {
        int ky = kk/3, kx = kk - ky*3;
        // ---- B tile: 64x64 weights for this (ky,kx) ----
        #pragma unroll
        for (int j = 0; j < 4; j++)
            ((float4*)sB)[j*256 + t] = wtask[kk*1024 + j*256 + t];
        // ---- A tile: im2col gather + BN-fold ----
        {
            int iy = 2*loy - 1 + ky;
            int ix = 2*lox - 1 + kx;
            float4* arow = (float4*)(sA + lm*68) + lq*JCNT;
            if ((unsigned)iy < (unsigned)HIN && (unsigned)ix < (unsigned)HIN) {
                const float4* src = (const float4*)(inb + (iy*HIN + ix)*64) + lq*JCNT;
                const float4* sc4 = (const float4*)s_sc + lq*JCNT;
                const float4* bi4 = (const float4*)s_bi + lq*JCNT;
                #pragma unroll
                for (int j = 0; j < JCNT; j++) {
                    float4 v = src[j];
                    float4 s4 = sc4[j];
                    float4 b4 = bi4[j];
                    v.x = fmaf(v.x, s4.x, b4.x);
                    v.y = fmaf(v.y, s4.y, b4.y);
                    v.z = fmaf(v.z, s4.z, b4.z);
                    v.w = fmaf(v.w, s4.w, b4.w);
                    arow[j] = v;
                }
            } else {
                float4 z = make_float4(0.f,0.f,0.f,0.f);
                #pragma unroll
                for (int j = 0; j < JCNT; j++) arow[j] = z;
            }
        }
        __syncthreads();
        // ---- GEMM: 64-deep k over this chunk ----
        const float* ap = sA + ig*68;
        #pragma unroll 8
        for (int k = 0; k < 64; k++) {
            float a[IT];
            #pragma unroll
            for (int i = 0; i < IT; i++) a[i] = ap[i*32*68 + k];
            float4 b0 = *(const float4*)(sB + k*64 + cg*8);
            float4 b1 = *(const float4*)(sB + k*64 + cg*8 + 4);
            #pragma unroll
            for (int i = 0; i < IT; i++) {
                acc[i][0] = fmaf(a[i], b0.x, acc[i][0]);
                acc[i][1] = fmaf(a[i], b0.y, acc[i][1]);
                acc[i][2] = fmaf(a[i], b0.z, acc[i][2]);
                acc[i][3] = fmaf(a[i], b0.w, acc[i][3]);
                acc[i][4] = fmaf(a[i], b1.x, acc[i][4]);
                acc[i][5] = fmaf(a[i], b1.y, acc[i][5]);
                acc[i][6] = fmaf(a[i], b1.z, acc[i][6]);
                acc[i][7] = fmaf(a[i], b1.w, acc[i][7]);
            }
        }
        __syncthreads();
    }

    // ---- epilogue: relu, stats, store / max-pool ----
    int co8 = cg*8;
    float lsum[8], lsq[8];
    #pragma unroll
    for (int j = 0; j < 8; j++) { lsum[j] = 0.f; lsq[j] = 0.f; }
    #pragma unroll
    for (int i = 0; i < IT; i++) {
        int item = ig + i*32;
        int g = m0 + item;
        if (g < MTASK) {
            #pragma unroll
            for (int j = 0; j < 8; j++) {
                float v = fmaxf(acc[i][j], 0.f);
                acc[i][j] = v;
                lsum[j] += v;
                lsq[j]  += v*v;
            }
            if (!LAST) {
                float4* dst = (float4*)(h_out + ((size_t)b*MTASK + g)*64 + co8);
                dst[0] = make_float4(acc[i][0],acc[i][1],acc[i][2],acc[i][3]);
                dst[1] = make_float4(acc[i][4],acc[i][5],acc[i][6],acc[i][7]);
            } else {
                int ee = g / POS;
                int* fp = (int*)(g_feat + ((size_t)(b*NE + ee))*64 + co8);
                #pragma unroll
                for (int j = 0; j < 8; j++)
                    atomicMax(&fp[j], __float_as_int(acc[i][j]));  // relu>=0: int order == float order
            }
        }
    }
    #pragma unroll
    for (int j = 0; j < 8; j++) {
        atomicAdd(&s_sum[co8+j], lsum[j]);
        atomicAdd(&s_sq[co8+j],  lsq[j]);
    }
    __syncthreads();
    if (t < 64) {
        atomicAdd(&g_sum[LNUM*NC + t],   s_sum[t]);
        atomicAdd(&g_sumsq[LNUM*NC + t], s_sq[t]);
    }
}

// ---------------- readout: normalize pooled feats, per-task matmul ----------------
__global__ __launch_bounds__(256) void readout_kernel(const float* __restrict__ w_ro,
                                                      float* __restrict__ out) {
    __shared__ float s_w[64*20];
    __shared__ float s_f[64*64];
    int b = blockIdx.x, t = threadIdx.x;
    for (int i = t; i < 1280; i += 256) s_w[i] = w_ro[(size_t)b*1280 + i];
    const float* fp = g_feat + (size_t)b*4096;
    for (int i = t; i < 4096; i += 256) {
        int c = i & 63;
        s_f[i] = fmaf(fp[i], g_scale[3*64+c], g_bias[3*64+c]);
    }
    __syncthreads();
    for (int idx = t; idx < 1280; idx += 256) {
        int e = idx/20, o = idx - e*20;
        float s = 0.f;
        const float* fe = s_f + e*64;
        #pragma unroll 16
        for (int c = 0; c < 64; c++) s = fmaf(fe[c], s_w[c*20+o], s);
        out[(size_t)b*1280 + idx] = s;
    }
}

// ---------------- launch ----------------
extern "C" void kernel_launch(void* const* d_in, const int* in_sizes, int n_in,
                              void* d_out, int out_size) {
    const float* x  = (const float*)d_in[0];
    const float* k1 = (const float*)d_in[1];
    const float* k2 = (const float*)d_in[2];
    const float* k3 = (const float*)d_in[3];
    const float* k4 = (const float*)d_in[4];
    const float* w  = (const float*)d_in[5];
    float* out = (float*)d_out;
    (void)in_sizes; (void)n_in; (void)out_size;

    const int smem12 = 256*68*4 + 64*64*4 + 4*64*4;   // 87040 B
    const int smem3  = 64*68*4  + 64*64*4 + 4*64*4;   // 34816 B
    cudaFuncSetAttribute(conv_kernel<1>, cudaFuncAttributeMaxDynamicSharedMemorySize, smem12);
    cudaFuncSetAttribute(conv_kernel<2>, cudaFuncAttributeMaxDynamicSharedMemorySize, smem12);
    cudaFuncSetAttribute(conv_kernel<3>, cudaFuncAttributeMaxDynamicSharedMemorySize, smem3);

    zero_kernel<<<1024, 256>>>();
    conv1_kernel<<<NB*NE, 256>>>(x, k1);
    finalize_kernel<<<1, 64>>>(0, 1.f/(NB*NE*196.f));
    conv_kernel<1><<<dim3(13, NB), 256, smem12>>>(k2);
    finalize_kernel<<<1, 64>>>(1, 1.f/(NB*NE*49.f));
    conv_kernel<2><<<dim3(4, NB), 256, smem12>>>(k3);
    finalize_kernel<<<1, 64>>>(2, 1.f/(NB*NE*16.f));
    conv_kernel<3><<<dim3(4, NB), 256, smem3>>>(k4);
    finalize_kernel<<<1, 64>>>(3, 1.f/(NB*NE*4.f));
    readout_kernel<<<NB, 256>>>(w, out);
}

// round 4
// speedup vs baseline: 1.0321x; 1.0321x over previous
#include <cuda_runtime.h>

#define NB 64
#define NE 64
#define NC 64
#define NO 20

// ---------------- device scratch (no allocs allowed) ----------------
__device__ float g_h1[(size_t)NB*NE*14*14*NC];   // conv1 raw relu out (205 MB)
__device__ float g_h2[(size_t)NB*NE*7*7*NC];     // conv2 raw relu out
__device__ float g_h3[(size_t)NB*NE*4*4*NC];     // conv3 raw relu out
__device__ float g_feat[NB*NE*NC];               // max-pooled raw conv4 relu
__device__ float g_sum[4*NC];
__device__ float g_sumsq[4*NC];
__device__ float g_scale[4*NC];                  // rsqrt(var+eps)
__device__ float g_bias[4*NC];                   // -mean*scale

// ---------------- zero stats + feat ----------------
__global__ void zero_kernel() {
    int i = blockIdx.x * 256 + threadIdx.x;
    if (i < 4*NC) { g_sum[i] = 0.f; g_sumsq[i] = 0.f; }
    if (i < NB*NE*NC) g_feat[i] = 0.f;
}

// ---------------- conv1: Cin=1, 28x28 -> 14x14x64 ----------------
__global__ __launch_bounds__(256) void conv1_kernel(const float* __restrict__ x,
                                                    const float* __restrict__ k1) {
    __shared__ float s_in[30*30];
    __shared__ float s_sum[NC];
    __shared__ float s_sq[NC];
    int be = blockIdx.x;
    int t = threadIdx.x;
    for (int i = t; i < 900; i += 256) s_in[i] = 0.f;
    if (t < NC) { s_sum[t] = 0.f; s_sq[t] = 0.f; }
    __syncthreads();
    const float* xp = x + (size_t)be * 784;
    for (int i = t; i < 784; i += 256) {
        int r = i / 28, c = i - r*28;
        s_in[(r+1)*30 + c + 1] = xp[i];
    }
    int cg = t & 15, ig = t >> 4;          // cg: 16 co-groups of 4, ig: 16 item groups
    int b = be >> 6;
    float4 w[9];
    const float4* kp = (const float4*)(k1 + (size_t)b * 576);
    #pragma unroll
    for (int j = 0; j < 9; j++) w[j] = kp[j*16 + cg];
    __syncthreads();
    float ls0=0,ls1=0,ls2=0,ls3=0, lq0=0,lq1=0,lq2=0,lq3=0;
    float* outp = g_h1 + (size_t)be * 196 * 64;
    for (int p = ig; p < 196; p += 16) {
        int oy = p / 14, ox = p - oy*14;
        float a0=0,a1=0,a2=0,a3=0;
        #pragma unroll
        for (int ky = 0; ky < 3; ky++)
        #pragma unroll
        for (int kx = 0; kx < 3; kx++) {
            float v = s_in[(2*oy+ky)*30 + 2*ox + kx];
            float4 ww = w[ky*3+kx];
            a0 = fmaf(v, ww.x, a0); a1 = fmaf(v, ww.y, a1);
            a2 = fmaf(v, ww.z, a2); a3 = fmaf(v, ww.w, a3);
        }
        a0 = fmaxf(a0, 0.f); a1 = fmaxf(a1, 0.f);
        a2 = fmaxf(a2, 0.f); a3 = fmaxf(a3, 0.f);
        ls0+=a0; ls1+=a1; ls2+=a2; ls3+=a3;
        lq0+=a0*a0; lq1+=a1*a1; lq2+=a2*a2; lq3+=a3*a3;
        ((float4*)(outp + p*64))[cg] = make_float4(a0,a1,a2,a3);
    }
    int co4 = cg*4;
    atomicAdd(&s_sum[co4+0], ls0); atomicAdd(&s_sum[co4+1], ls1);
    atomicAdd(&s_sum[co4+2], ls2); atomicAdd(&s_sum[co4+3], ls3);
    atomicAdd(&s_sq[co4+0], lq0); atomicAdd(&s_sq[co4+1], lq1);
    atomicAdd(&s_sq[co4+2], lq2); atomicAdd(&s_sq[co4+3], lq3);
    __syncthreads();
    if (t < NC) {
        atomicAdd(&g_sum[t], s_sum[t]);
        atomicAdd(&g_sumsq[t], s_sq[t]);
    }
}

// ---------------- per-layer BN stats finalize ----------------
__global__ void finalize_kernel(int layer, float invN) {
    int c = threadIdx.x;
    float s = g_sum[layer*NC + c];
    float q = g_sumsq[layer*NC + c];
    float m = s * invN;
    float v = q * invN - m*m;
    float sc = rsqrtf(v + 1e-3f);
    g_scale[layer*NC + c] = sc;
    g_bias[layer*NC + c] = -m * sc;
}

// ---------------- generic conv layers 2-4 (implicit GEMM per task) ----------------
// LNUM=1: h1(14x14) -> h2(7x7); LNUM=2: h2 -> h3(4x4); LNUM=3: h3 -> g_feat (max), LAST
template<int LNUM>
__global__ __launch_bounds__(256, 2) void conv_kernel(const float* __restrict__ kw) {
    constexpr int HIN    = (LNUM==1) ? 14 : (LNUM==2) ? 7 : 4;
    constexpr int HOUT   = (LNUM==1) ? 7  : (LNUM==2) ? 4 : 2;
    constexpr int SPREV  = LNUM - 1;
    constexpr int TILE_M = (LNUM==3) ? 64 : 256;
    constexpr int IT     = (LNUM==3) ? 2  : 8;
    constexpr bool LAST  = (LNUM==3);
    constexpr int POS    = HOUT*HOUT;
    constexpr int MTASK  = NE*POS;

    extern __shared__ float sm[];
    float* sA   = sm;                    // TILE_M rows x 68 floats (64 used + pad)
    float* sB   = sm + TILE_M*68;        // 64 ci x 64 co (co fastest)
    float* s_sc = sB + 64*64;
    float* s_bi = s_sc + 64;
    float* s_sum= s_bi + 64;
    float* s_sq = s_sum + 64;
    int*   s_ri = (int*)(s_sq + 64);     // TILE_M row-info entries

    const float* h_prev = (LNUM==1) ? g_h1 : (LNUM==2) ? g_h2 : g_h3;
    float* h_out        = (LNUM==1) ? g_h2 : g_h3;

    int b  = blockIdx.y;
    int m0 = blockIdx.x * TILE_M;
    int t  = threadIdx.x;
    if (t < 64) {
        s_sc[t] = g_scale[SPREV*NC + t];
        s_bi[t] = g_bias[SPREV*NC + t];
        s_sum[t] = 0.f; s_sq[t] = 0.f;
    }
    if (t < TILE_M) {
        int gi  = m0 + t;
        int gic = min(gi, MTASK-1);
        int e  = gic / POS;
        int p  = gic - e*POS;
        s_ri[t] = (e << 16) | ((p / HOUT) << 8) | (p % HOUT);
    }

    // loader: 16 threads per item row (coalesced 256B per row)
    int lr = t >> 4;     // row-within-pass (0..15)
    int lj = t & 15;     // float4 (channel group) within row

    // compute: cg in 0..7 selects couts {cg*4..cg*4+3} and {32+cg*4..35+cg*4}
    int cg = t & 7, ig = t >> 3;
    float acc[IT][8];
    #pragma unroll
    for (int i = 0; i < IT; i++)
        #pragma unroll
        for (int j = 0; j < 8; j++) acc[i][j] = 0.f;

    __syncthreads();

    // BN fold coefficients for this loader's channel group (invariant over kk)
    float4 f_s = ((const float4*)s_sc)[lj];
    float4 f_b = ((const float4*)s_bi)[lj];

    const float4* wtask = (const float4*)(kw + (size_t)b*9*64*64);
    const float* taskin = h_prev + (size_t)b*NE*HIN*HIN*64;

    for (int kk = 0; kk < 9; kk++) {
        int ky = kk/3, kx = kk - ky*3;
        // ---- B tile: 64x64 weights for this (ky,kx) ----
        #pragma unroll
        for (int j = 0; j < 4; j++)
            ((float4*)sB)[j*256 + t] = wtask[kk*1024 + j*256 + t];
        // ---- A tile: coalesced im2col gather + BN-fold ----
        #pragma unroll
        for (int rr = 0; rr < TILE_M/16; rr++) {
            int row  = rr*16 + lr;
            int info = s_ri[row];
            int e  = info >> 16;
            int oy = (info >> 8) & 255;
            int ox = info & 255;
            int iy = 2*oy - 1 + ky;
            int ix = 2*ox - 1 + kx;
            float4 v;
            if ((unsigned)iy < (unsigned)HIN && (unsigned)ix < (unsigned)HIN) {
                v = ((const float4*)(taskin + ((size_t)e*HIN*HIN + iy*HIN + ix)*64))[lj];
                v.x = fmaf(v.x, f_s.x, f_b.x);
                v.y = fmaf(v.y, f_s.y, f_b.y);
                v.z = fmaf(v.z, f_s.z, f_b.z);
                v.w = fmaf(v.w, f_s.w, f_b.w);
            } else {
                v = make_float4(0.f,0.f,0.f,0.f);
            }
            ((float4*)(sA + row*68))[lj] = v;
        }
        __syncthreads();
        // ---- GEMM: 64-deep k, staged 4 k's at a time via float4 A reads ----
        const float* ap = sA + ig*68;
        #pragma unroll 2
        for (int k4 = 0; k4 < 64; k4 += 4) {
            float4 av[IT];
            #pragma unroll
            for (int i = 0; i < IT; i++)
                av[i] = *(const float4*)(ap + i*32*68 + k4);
            #pragma unroll
            for (int q = 0; q < 4; q++) {
                const float* bp = sB + (k4+q)*64 + cg*4;
                float4 b0 = *(const float4*)(bp);
                float4 b1 = *(const float4*)(bp + 32);
                #pragma unroll
                for (int i = 0; i < IT; i++) {
                    float a = (q==0) ? av[i].x : (q==1) ? av[i].y : (q==2) ? av[i].z : av[i].w;
                    acc[i][0] = fmaf(a, b0.x, acc[i][0]);
                    acc[i][1] = fmaf(a, b0.y, acc[i][1]);
                    acc[i][2] = fmaf(a, b0.z, acc[i][2]);
                    acc[i][3] = fmaf(a, b0.w, acc[i][3]);
                    acc[i][4] = fmaf(a, b1.x, acc[i][4]);
                    acc[i][5] = fmaf(a, b1.y, acc[i][5]);
                    acc[i][6] = fmaf(a, b1.z, acc[i][6]);
                    acc[i][7] = fmaf(a, b1.w, acc[i][7]);
                }
            }
        }
        __syncthreads();
    }

    // ---- epilogue: relu, stats, store / max-pool ----
    int co_lo = cg*4;            // couts co_lo..co_lo+3 (acc[][0..3])
    int co_hi = cg*4 + 32;       // couts co_hi..co_hi+3 (acc[][4..7])
    float lsum[8], lsq[8];
    #pragma unroll
    for (int j = 0; j < 8; j++) { lsum[j] = 0.f; lsq[j] = 0.f; }
    #pragma unroll
    for (int i = 0; i < IT; i++) {
        int item = ig + i*32;
        int g = m0 + item;
        if (g < MTASK) {
            #pragma unroll
            for (int j = 0; j < 8; j++) {
                float v = fmaxf(acc[i][j], 0.f);
                acc[i][j] = v;
                lsum[j] += v;
                lsq[j]  += v*v;
            }
            if (!LAST) {
                float4* dst = (float4*)(h_out + ((size_t)b*MTASK + g)*64);
                dst[cg]     = make_float4(acc[i][0],acc[i][1],acc[i][2],acc[i][3]);
                dst[cg + 8] = make_float4(acc[i][4],acc[i][5],acc[i][6],acc[i][7]);
            } else {
                int ee = g / POS;
                int* fp = (int*)(g_feat + ((size_t)(b*NE + ee))*64);
                #pragma unroll
                for (int j = 0; j < 4; j++)
                    atomicMax(&fp[co_lo+j], __float_as_int(acc[i][j]));
                #pragma unroll
                for (int j = 0; j < 4; j++)
                    atomicMax(&fp[co_hi+j], __float_as_int(acc[i][4+j]));
            }
        }
    }
    #pragma unroll
    for (int j = 0; j < 4; j++) {
        atomicAdd(&s_sum[co_lo+j], lsum[j]);
        atomicAdd(&s_sq[co_lo+j],  lsq[j]);
        atomicAdd(&s_sum[co_hi+j], lsum[4+j]);
        atomicAdd(&s_sq[co_hi+j],  lsq[4+j]);
    }
    __syncthreads();
    if (t < 64) {
        atomicAdd(&g_sum[LNUM*NC + t],   s_sum[t]);
        atomicAdd(&g_sumsq[LNUM*NC + t], s_sq[t]);
    }
}

// ---------------- readout: normalize pooled feats, per-task matmul ----------------
__global__ __launch_bounds__(256) void readout_kernel(const float* __restrict__ w_ro,
                                                      float* __restrict__ out) {
    __shared__ float s_w[64*20];
    __shared__ float s_f[64*64];
    int b = blockIdx.x, t = threadIdx.x;
    for (int i = t; i < 1280; i += 256) s_w[i] = w_ro[(size_t)b*1280 + i];
    const float* fp = g_feat + (size_t)b*4096;
    for (int i = t; i < 4096; i += 256) {
        int c = i & 63;
        s_f[i] = fmaf(fp[i], g_scale[3*64+c], g_bias[3*64+c]);
    }
    __syncthreads();
    for (int idx = t; idx < 1280; idx += 256) {
        int e = idx/20, o = idx - e*20;
        float s = 0.f;
        const float* fe = s_f + e*64;
        #pragma unroll 16
        for (int c = 0; c < 64; c++) s = fmaf(fe[c], s_w[c*20+o], s);
        out[(size_t)b*1280 + idx] = s;
    }
}

// ---------------- launch ----------------
extern "C" void kernel_launch(void* const* d_in, const int* in_sizes, int n_in,
                              void* d_out, int out_size) {
    const float* x  = (const float*)d_in[0];
    const float* k1 = (const float*)d_in[1];
    const float* k2 = (const float*)d_in[2];
    const float* k3 = (const float*)d_in[3];
    const float* k4 = (const float*)d_in[4];
    const float* w  = (const float*)d_in[5];
    float* out = (float*)d_out;
    (void)in_sizes; (void)n_in; (void)out_size;

    const int smem12 = 256*68*4 + 64*64*4 + 4*64*4 + 256*4;   // A + B + stats + rowinfo
    const int smem3  = 64*68*4  + 64*64*4 + 4*64*4 + 64*4;
    cudaFuncSetAttribute(conv_kernel<1>, cudaFuncAttributeMaxDynamicSharedMemorySize, smem12);
    cudaFuncSetAttribute(conv_kernel<2>, cudaFuncAttributeMaxDynamicSharedMemorySize, smem12);
    cudaFuncSetAttribute(conv_kernel<3>, cudaFuncAttributeMaxDynamicSharedMemorySize, smem3);

    zero_kernel<<<1024, 256>>>();
    conv1_kernel<<<NB*NE, 256>>>(x, k1);
    finalize_kernel<<<1, 64>>>(0, 1.f/(NB*NE*196.f));
    conv_kernel<1><<<dim3(13, NB), 256, smem12>>>(k2);
    finalize_kernel<<<1, 64>>>(1, 1.f/(NB*NE*49.f));
    conv_kernel<2><<<dim3(4, NB), 256, smem12>>>(k3);
    finalize_kernel<<<1, 64>>>(2, 1.f/(NB*NE*16.f));
    conv_kernel<3><<<dim3(4, NB), 256, smem3>>>(k4);
    finalize_kernel<<<1, 64>>>(3, 1.f/(NB*NE*4.f));
    readout_kernel<<<NB, 256>>>(w, out);
}